// round 3
// baseline (speedup 1.0000x reference)
#include <cuda_runtime.h>
#include <cuda_bf16.h>

// AngleTensor: out[b,i,j,k] = mask * arccos( u_ij . u_ik ),  u_ij = (p_j-p_i)/d_ij
// B=8, N=128 fixed.
//
// grid = (N, B, 2): block (i, b, z) computes rows j in [64z, 64z+64).
// (z-split doubles resident warps: 4096 -> 8192, occupancy ceiling 43% -> 86%.)
// 128 threads: thread t owns k = 4*(t&31)..+3, walks j = 64z + (t>>5) step 4
// (warp-uniform j -> broadcast LDS, coalesced float4 STG).
// Shared sh[j] = float4(ux, uy, uz, z) with zero vector + z=0 on masked rows.
// acos via A&S 4.4.45 (abs err 6.7e-5 rad). Diagonal j==k fixed post-loop.

#define N_FIXED 128
#define PI_F 3.14159265358979f

__global__ __launch_bounds__(128) void angle_kernel(
    const float* __restrict__ pos,   // (B, N, 3)
    const float* __restrict__ dist,  // (B, N, N)
    float* __restrict__ out)         // (B, N, N, N)
{
    const int i = blockIdx.x;
    const int b = blockIdx.y;
    const int z = blockIdx.z;        // j-half selector
    const int t = threadIdx.x;
    const int N = N_FIXED;

    __shared__ float4 sh[N_FIXED];

    const float pix = pos[(b * N + i) * 3 + 0];
    const float piy = pos[(b * N + i) * 3 + 1];
    const float piz = pos[(b * N + i) * 3 + 2];

    {
        const int j = t;
        const float px = pos[(b * N + j) * 3 + 0];
        const float py = pos[(b * N + j) * 3 + 1];
        const float pz = pos[(b * N + j) * 3 + 2];
        const float d  = dist[((size_t)b * N + i) * N + j];
        const float inv = (d > 0.0f) ? (1.0f / d) : 0.0f;  // 0 on j==i -> zero vec
        const float zz  = (j != i && d > 0.0f) ? 1.0f : 0.0f;
        sh[j] = make_float4((px - pix) * inv, (py - piy) * inv, (pz - piz) * inv, zz);
    }
    __syncthreads();

    const int k0 = (t & 31) * 4;   // owns columns k0..k0+3
    const int jq = t >> 5;         // j phase (warp-uniform)
    const int jdiag = k0 + jq;     // the single (j,k) diagonal this thread can emit

    const float4 u0 = sh[k0 + 0];
    const float4 u1 = sh[k0 + 1];
    const float4 u2 = sh[k0 + 2];
    const float4 u3 = sh[k0 + 3];
    const float zk0 = u0.w, zk1 = u1.w, zk2 = u2.w, zk3 = u3.w;

    float* orow = out + (((size_t)b * N + i) * N) * N;

    const int jbeg = z * 64 + jq;
    const int jend = z * 64 + 64;

#pragma unroll 4
    for (int j = jbeg; j < jend; j += 4) {
        const float4 uj = sh[j];
        const float  zj = uj.w;

        float c0 = uj.x * u0.x + uj.y * u0.y + uj.z * u0.z;
        float c1 = uj.x * u1.x + uj.y * u1.y + uj.z * u1.z;
        float c2 = uj.x * u2.x + uj.y * u2.y + uj.z * u2.z;
        float c3 = uj.x * u3.x + uj.y * u3.y + uj.z * u3.z;

        const float x0 = fabsf(c0), x1 = fabsf(c1), x2 = fabsf(c2), x3 = fabsf(c3);

        const float y0 = fmaxf(1.0f - x0, 1e-12f);
        const float y1 = fmaxf(1.0f - x1, 1e-12f);
        const float y2 = fmaxf(1.0f - x2, 1e-12f);
        const float y3 = fmaxf(1.0f - x3, 1e-12f);

        const float s0 = y0 * rsqrtf(y0);   // sqrt(y)
        const float s1 = y1 * rsqrtf(y1);
        const float s2 = y2 * rsqrtf(y2);
        const float s3 = y3 * rsqrtf(y3);

        // A&S 4.4.45 polynomial in |x|
        float p0 = fmaf(x0, -0.0187293f, 0.0742610f);
        float p1 = fmaf(x1, -0.0187293f, 0.0742610f);
        float p2 = fmaf(x2, -0.0187293f, 0.0742610f);
        float p3 = fmaf(x3, -0.0187293f, 0.0742610f);
        p0 = fmaf(p0, x0, -0.2121144f);
        p1 = fmaf(p1, x1, -0.2121144f);
        p2 = fmaf(p2, x2, -0.2121144f);
        p3 = fmaf(p3, x3, -0.2121144f);
        p0 = fmaf(p0, x0, 1.5707288f);
        p1 = fmaf(p1, x1, 1.5707288f);
        p2 = fmaf(p2, x2, 1.5707288f);
        p3 = fmaf(p3, x3, 1.5707288f);

        const float b0 = s0 * p0;
        const float b1 = s1 * p1;
        const float b2 = s2 * p2;
        const float b3 = s3 * p3;

        const float a0 = (c0 < 0.0f) ? (PI_F - b0) : b0;
        const float a1 = (c1 < 0.0f) ? (PI_F - b1) : b1;
        const float a2 = (c2 < 0.0f) ? (PI_F - b2) : b2;
        const float a3 = (c3 < 0.0f) ? (PI_F - b3) : b3;

        float4 v;
        v.x = a0 * (zj * zk0);
        v.y = a1 * (zj * zk1);
        v.z = a2 * (zj * zk2);
        v.w = a3 * (zj * zk3);

        *reinterpret_cast<float4*>(orow + (size_t)j * N + k0) = v;
    }

    // fix the single diagonal (j==k) element, only from the block owning that j-half
    if ((jdiag >> 6) == z)
        orow[(size_t)jdiag * N + jdiag] = 0.0f;
}

extern "C" void kernel_launch(void* const* d_in, const int* in_sizes, int n_in,
                              void* d_out, int out_size) {
    const float* pos  = (const float*)d_in[0];   // positions (B, N, 3)
    const float* dist = (const float*)d_in[1];   // dist_matrix (B, N, N)
    float* out = (float*)d_out;                  // (B, N, N, N) fp32

    const int N = (int)(3LL * in_sizes[1] / in_sizes[0]);   // = 128
    const int B = in_sizes[0] / (3 * N);                    // = 8

    dim3 grid(N, B, 2);
    angle_kernel<<<grid, 128>>>(pos, dist, out);
}